// round 2
// baseline (speedup 1.0000x reference)
#include <cuda_runtime.h>
#include <cstdint>

#define B 512
#define COND 64
#define NN 256
#define NE 32640
#define OUT2 65280
#define D1 256
#define D2 512
#define D3 1024
#define EPAD 32768

// ---------------- scratch (static device globals; no allocation) ----------------
__device__ float g_h3[B * D3];                 // 2 MB: last hidden layer, selected expert
__device__ int g_perm[B];
__device__ int g_cnt[2];
__device__ unsigned char g_edges[B * EPAD];    // 16.8 MB: edge bits as bytes

// ---------------- f32x2 helpers ----------------
__device__ __forceinline__ unsigned long long pack2(float a, float b) {
    unsigned long long r;
    asm("mov.b64 %0, {%1, %2};" : "=l"(r) : "f"(a), "f"(b));
    return r;
}
__device__ __forceinline__ void unpack2(unsigned long long v, float& a, float& b) {
    asm("mov.b64 {%0, %1}, %2;" : "=f"(a), "=f"(b) : "l"(v));
}
__device__ __forceinline__ void fma2(unsigned long long& d, unsigned long long a, unsigned long long b) {
    asm("fma.rn.f32x2 %0, %1, %2, %0;" : "+l"(d) : "l"(a), "l"(b));
}

// ---------------- kernel A: partition batches by expert ----------------
__global__ void k_group(const float* __restrict__ x) {
    __shared__ int cnt[2];
    int t = threadIdx.x;
    if (t < 2) cnt[t] = 0;
    __syncthreads();
    int big = (x[t * COND] > 0.0f) ? 1 : 0;
    int p = atomicAdd(&cnt[big ? 0 : 1], 1);
    g_perm[big ? p : (B - 1 - p)] = t;
    __syncthreads();
    if (t == 0) { g_cnt[0] = cnt[0]; g_cnt[1] = cnt[1]; }
}

// ---------------- kernel B: hidden trunk 64->256->512->1024 ----------------
// 64 blocks x 256 threads; each block handles 8 batches (register-blocked across batches).
__global__ __launch_bounds__(256) void k_hidden(
    const float* __restrict__ x,
    const float* __restrict__ bw0, const float* __restrict__ bb0,
    const float* __restrict__ bw1, const float* __restrict__ bb1,
    const float* __restrict__ bw2, const float* __restrict__ bb2,
    const float* __restrict__ sw0, const float* __restrict__ sb0,
    const float* __restrict__ sw1, const float* __restrict__ sb1,
    const float* __restrict__ sw2, const float* __restrict__ sb2)
{
    __shared__ float xs[8][COND];
    __shared__ float h1s[8][D1];
    __shared__ float h2s[8][D2];
    __shared__ int bi[8];

    int t = threadIdx.x;
    int g = blockIdx.x;
    if (t < 8) bi[t] = g_perm[g * 8 + t];
    __syncthreads();
    int nbig = g_cnt[0];

    for (int i = t; i < 8 * COND; i += 256) {
        int s = i >> 6, k = i & 63;
        xs[s][k] = x[bi[s] * COND + k];
    }
    __syncthreads();

    for (int ex = 0; ex < 2; ex++) {
        bool own[8];
        bool anyown = false;
#pragma unroll
        for (int s = 0; s < 8; s++) {
            own[s] = (((g * 8 + s) < nbig ? 0 : 1) == ex);
            anyown |= own[s];
        }
        if (!anyown) { continue; }

        const float* W0 = ex ? sw0 : bw0; const float* B0 = ex ? sb0 : bb0;
        const float* W1 = ex ? sw1 : bw1; const float* B1 = ex ? sb1 : bb1;
        const float* W2 = ex ? sw2 : bw2; const float* B2 = ex ? sb2 : bb2;

        // L1: 64 -> 256 (thread t computes neuron t for 8 batches)
        {
            float acc[8];
#pragma unroll
            for (int s = 0; s < 8; s++) acc[s] = 0.f;
#pragma unroll 4
            for (int k = 0; k < COND; k++) {
                float w = W0[k * D1 + t];
#pragma unroll
                for (int s = 0; s < 8; s++) acc[s] = fmaf(xs[s][k], w, acc[s]);
            }
            float bb = B0[t];
#pragma unroll
            for (int s = 0; s < 8; s++) h1s[s][t] = fmaxf(acc[s] + bb, 0.f);
        }
        __syncthreads();

        // L2: 256 -> 512 (neurons t, t+256)
        {
            float a0[8], a1[8];
#pragma unroll
            for (int s = 0; s < 8; s++) { a0[s] = 0.f; a1[s] = 0.f; }
#pragma unroll 4
            for (int k = 0; k < D1; k++) {
                float w0 = W1[k * D2 + t];
                float w1 = W1[k * D2 + t + 256];
#pragma unroll
                for (int s = 0; s < 8; s++) {
                    float h = h1s[s][k];
                    a0[s] = fmaf(h, w0, a0[s]);
                    a1[s] = fmaf(h, w1, a1[s]);
                }
            }
            float b0v = B1[t], b1v = B1[t + 256];
#pragma unroll
            for (int s = 0; s < 8; s++) {
                h2s[s][t]       = fmaxf(a0[s] + b0v, 0.f);
                h2s[s][t + 256] = fmaxf(a1[s] + b1v, 0.f);
            }
        }
        __syncthreads();

        // L3: 512 -> 1024 (neurons t + q*256)
        {
            float acc[4][8];
#pragma unroll
            for (int q = 0; q < 4; q++)
#pragma unroll
                for (int s = 0; s < 8; s++) acc[q][s] = 0.f;
#pragma unroll 2
            for (int k = 0; k < D2; k++) {
                float w0 = W2[k * D3 + t];
                float w1 = W2[k * D3 + t + 256];
                float w2 = W2[k * D3 + t + 512];
                float w3 = W2[k * D3 + t + 768];
#pragma unroll
                for (int s = 0; s < 8; s++) {
                    float h = h2s[s][k];
                    acc[0][s] = fmaf(h, w0, acc[0][s]);
                    acc[1][s] = fmaf(h, w1, acc[1][s]);
                    acc[2][s] = fmaf(h, w2, acc[2][s]);
                    acc[3][s] = fmaf(h, w3, acc[3][s]);
                }
            }
#pragma unroll
            for (int q = 0; q < 4; q++) {
                float bq = B2[t + q * 256];
#pragma unroll
                for (int s = 0; s < 8; s++) {
                    if (own[s]) g_h3[bi[s] * D3 + t + q * 256] = fmaxf(acc[q][s] + bq, 0.f);
                }
            }
        }
        __syncthreads();
    }
}

// ---------------- kernel C: margin GEMM (fp32, f32x2 FMA) ----------------
// margins[rows x 32640] = h3 @ (W3[:,2e] - W3[:,2e+1]); bit = margin + db + dg >= 0.
#define MT 128
#define NT 128
#define KT 16
#define ASTRIDE 20

__global__ __launch_bounds__(256) void k_gemm(
    const float* __restrict__ gumbel,
    const float* __restrict__ bw3, const float* __restrict__ bb3,
    const float* __restrict__ sw3, const float* __restrict__ sb3)
{
    __shared__ float a_s[MT * ASTRIDE];    // a_s[m][k], padded stride
    __shared__ float b_s[KT * NT];         // b_s[k][n]
    __shared__ int batch_s[MT];

    int t = threadIdx.x;
    int tx = t & 15, ty = t >> 4;
    int mt = blockIdx.y;             // 0..7: 4 row tiles per expert
    int ex = mt >> 2;
    int nbig = g_cnt[0];
    int base = ex ? nbig : 0;
    int cnt  = ex ? (B - nbig) : nbig;
    int mrow0 = (mt & 3) * MT;
    if (mrow0 >= cnt) return;
    int n0 = blockIdx.x * NT;        // 255 edge tiles, 255*128 = 32640 exactly

    const float* W3 = ex ? sw3 : bw3;
    const float* B3 = ex ? sb3 : bb3;

    for (int m = t; m < MT; m += 256) {
        int r = mrow0 + m;
        batch_s[m] = g_perm[base + (r < cnt ? r : 0)];
    }
    __syncthreads();

    unsigned long long acc[8][4];
#pragma unroll
    for (int i = 0; i < 8; i++)
#pragma unroll
        for (int j = 0; j < 4; j++) acc[i][j] = 0ULL;

    int lm = t >> 1;
    int lk = (t & 1) * 8;
    const float* aptr = g_h3 + batch_s[lm] * D3 + lk;

    for (int k0 = 0; k0 < D3; k0 += KT) {
        __syncthreads();
        // A tile: 128 m x 16 k
        float4 av0 = *(const float4*)(aptr + k0);
        float4 av1 = *(const float4*)(aptr + k0 + 4);
        *(float4*)&a_s[lm * ASTRIDE + lk]     = av0;
        *(float4*)&a_s[lm * ASTRIDE + lk + 4] = av1;
        // B tile: wdiff on the fly, 16 k x 128 edges (adjacent W3 column pairs)
#pragma unroll
        for (int p = 0; p < 4; p++) {
            int idx = p * 256 + t;
            int kk = idx >> 6;
            int q  = idx & 63;
            float4 w = *(const float4*)(W3 + (size_t)(k0 + kk) * OUT2 + 2 * n0 + 4 * q);
            *(float2*)&b_s[kk * NT + 2 * q] = make_float2(w.x - w.y, w.z - w.w);
        }
        __syncthreads();
#pragma unroll
        for (int k = 0; k < KT; k++) {
            ulonglong2 bA = *(const ulonglong2*)&b_s[k * NT + tx * 8];
            ulonglong2 bB = *(const ulonglong2*)&b_s[k * NT + tx * 8 + 4];
#pragma unroll
            for (int i = 0; i < 8; i++) {
                float a = a_s[(ty + 16 * i) * ASTRIDE + k];
                unsigned long long a2 = pack2(a, a);
                fma2(acc[i][0], a2, bA.x);
                fma2(acc[i][1], a2, bA.y);
                fma2(acc[i][2], a2, bB.x);
                fma2(acc[i][3], a2, bB.y);
            }
        }
    }

    // epilogue: add bias diff + gumbel diff, emit bits
    int nb = n0 + tx * 8;
    float bd[8];
#pragma unroll
    for (int jj = 0; jj < 8; jj++) {
        float2 bp = *(const float2*)(B3 + 2 * (nb + jj));
        bd[jj] = bp.x - bp.y;
    }
#pragma unroll
    for (int i = 0; i < 8; i++) {
        int r = mrow0 + ty + 16 * i;
        if (r >= cnt) continue;
        int bb = batch_s[ty + 16 * i];
        const float* gp = gumbel + (size_t)bb * OUT2 + 2 * nb;
        unsigned long long ov = 0;
#pragma unroll
        for (int j = 0; j < 4; j++) {
            float m0, m1;
            unpack2(acc[i][j], m0, m1);
            float2 ga = *(const float2*)(gp + 4 * j);
            float2 gb = *(const float2*)(gp + 4 * j + 2);
            m0 += bd[2 * j]     + (ga.x - ga.y);
            m1 += bd[2 * j + 1] + (gb.x - gb.y);
            if (m0 >= 0.f) ov |= 1ULL << (8 * (2 * j));
            if (m1 >= 0.f) ov |= 1ULL << (8 * (2 * j + 1));
        }
        *(unsigned long long*)&g_edges[(size_t)bb * EPAD + nb] = ov;
    }
}

// ---------------- kernel D: expand bits -> symmetric 256x256 fp32 ----------------
__global__ __launch_bounds__(256) void k_expand(float* __restrict__ out) {
    int b = blockIdx.x;
    int iblk = blockIdx.y;
    const unsigned char* eb = g_edges + (size_t)b * EPAD;
    float* ob = out + (size_t)b * (NN * NN);
    int t = threadIdx.x;
#pragma unroll
    for (int p = 0; p < 4; p++) {
        int idx = p * 256 + t;
        int il = idx >> 6;
        int jq = idx & 63;
        int i = iblk * 16 + il;
        int j0 = jq * 4;
        float v[4];
#pragma unroll
        for (int c = 0; c < 4; c++) {
            int j = j0 + c;
            float val = 0.f;
            if (j != i) {
                int lo = (j < i) ? j : i;
                int hi = (j < i) ? i : j;
                int e = (lo * (511 - lo)) / 2 + (hi - lo - 1);
                val = (float)eb[e];
            }
            v[c] = val;
        }
        *(float4*)&ob[i * NN + j0] = make_float4(v[0], v[1], v[2], v[3]);
    }
}

// ---------------- launch ----------------
extern "C" void kernel_launch(void* const* d_in, const int* in_sizes, int n_in,
                              void* d_out, int out_size) {
    const float* x      = (const float*)d_in[0];
    const float* gumbel = (const float*)d_in[1];

    const float *bw[4], *bb[4], *sw[4], *sb[4];
    if (in_sizes[4] == 16384) {
        // interleaved per layer: bw_l, bb_l, sw_l, sb_l
        for (int l = 0; l < 4; l++) {
            bw[l] = (const float*)d_in[2 + 4 * l];
            bb[l] = (const float*)d_in[3 + 4 * l];
            sw[l] = (const float*)d_in[4 + 4 * l];
            sb[l] = (const float*)d_in[5 + 4 * l];
        }
    } else {
        // grouped: all big, then all small
        for (int l = 0; l < 4; l++) {
            bw[l] = (const float*)d_in[2 + 2 * l];
            bb[l] = (const float*)d_in[3 + 2 * l];
            sw[l] = (const float*)d_in[10 + 2 * l];
            sb[l] = (const float*)d_in[11 + 2 * l];
        }
    }
    float* out = (float*)d_out;

    k_group<<<1, B>>>(x);
    k_hidden<<<64, 256>>>(x,
        bw[0], bb[0], bw[1], bb[1], bw[2], bb[2],
        sw[0], sb[0], sw[1], sb[1], sw[2], sb[2]);
    k_gemm<<<dim3(255, 8), 256>>>(gumbel, bw[3], bb[3], sw[3], sb[3]);
    k_expand<<<dim3(B, 16), 256>>>(out);
}

// round 4
// speedup vs baseline: 2.0258x; 2.0258x over previous
#include <cuda_runtime.h>
#include <cuda_bf16.h>
#include <cstdint>

#define B 512
#define COND 64
#define NN 256
#define NE 32640
#define OUT2 65280
#define D1 256
#define D2 512
#define D3 1024
#define EPAD 32768

// ---------------- scratch ----------------
__device__ __nv_bfloat16 g_h3hi[B * D3];
__device__ __nv_bfloat16 g_h3lo[B * D3];
__device__ int g_perm[B];
__device__ int g_cnt[2];
__device__ unsigned char g_edges[B * EPAD];

// ---------------- helpers ----------------
__device__ __forceinline__ uint32_t smem_u32(const void* p) {
    uint32_t a;
    asm("{ .reg .u64 t; cvta.to.shared.u64 t, %1; cvt.u32.u64 %0, t; }" : "=r"(a) : "l"(p));
    return a;
}
__device__ __forceinline__ void ldm_x4(uint32_t& r0, uint32_t& r1, uint32_t& r2, uint32_t& r3,
                                       uint32_t addr) {
    asm volatile("ldmatrix.sync.aligned.m8n8.x4.shared.b16 {%0,%1,%2,%3}, [%4];"
                 : "=r"(r0), "=r"(r1), "=r"(r2), "=r"(r3) : "r"(addr));
}
__device__ __forceinline__ void mma_bf16(float* c, uint32_t a0, uint32_t a1, uint32_t a2,
                                         uint32_t a3, uint32_t b0, uint32_t b1) {
    asm volatile(
        "mma.sync.aligned.m16n8k16.row.col.f32.bf16.bf16.f32 "
        "{%0,%1,%2,%3}, {%4,%5,%6,%7}, {%8,%9}, {%0,%1,%2,%3};"
        : "+f"(c[0]), "+f"(c[1]), "+f"(c[2]), "+f"(c[3])
        : "r"(a0), "r"(a1), "r"(a2), "r"(a3), "r"(b0), "r"(b1));
}

// ---------------- kernel A: partition by expert ----------------
__global__ void k_group(const float* __restrict__ x) {
    __shared__ int cnt[2];
    int t = threadIdx.x;
    if (t < 2) cnt[t] = 0;
    __syncthreads();
    int big = (x[t * COND] > 0.0f) ? 1 : 0;
    int p = atomicAdd(&cnt[big ? 0 : 1], 1);
    g_perm[big ? p : (B - 1 - p)] = t;
    __syncthreads();
    if (t == 0) { g_cnt[0] = cnt[0]; g_cnt[1] = cnt[1]; }
}

// ---------------- kernel B: trunk 64->256->512->1024, outputs bf16 hi/lo ----------------
__global__ __launch_bounds__(256) void k_hidden(
    const float* __restrict__ x,
    const float* __restrict__ bw0, const float* __restrict__ bb0,
    const float* __restrict__ bw1, const float* __restrict__ bb1,
    const float* __restrict__ bw2, const float* __restrict__ bb2,
    const float* __restrict__ sw0, const float* __restrict__ sb0,
    const float* __restrict__ sw1, const float* __restrict__ sb1,
    const float* __restrict__ sw2, const float* __restrict__ sb2)
{
    __shared__ float xs[8][COND];
    __shared__ float h1s[8][D1];
    __shared__ float h2s[8][D2];
    __shared__ int bi[8];

    int t = threadIdx.x;
    int g = blockIdx.x;
    int qh = blockIdx.y;
    if (t < 8) bi[t] = g_perm[g * 8 + t];
    __syncthreads();
    int nbig = g_cnt[0];

    for (int i = t; i < 8 * COND; i += 256) {
        int s = i >> 6, k = i & 63;
        xs[s][k] = x[bi[s] * COND + k];
    }
    __syncthreads();

    for (int ex = 0; ex < 2; ex++) {
        bool own[8]; bool anyown = false;
#pragma unroll
        for (int s = 0; s < 8; s++) {
            own[s] = (((g * 8 + s) < nbig ? 0 : 1) == ex);
            anyown |= own[s];
        }
        if (!anyown) continue;

        const float* W0 = ex ? sw0 : bw0; const float* B0 = ex ? sb0 : bb0;
        const float* W1 = ex ? sw1 : bw1; const float* B1 = ex ? sb1 : bb1;
        const float* W2 = ex ? sw2 : bw2; const float* B2 = ex ? sb2 : bb2;

        { // L1
            float acc[8];
#pragma unroll
            for (int s = 0; s < 8; s++) acc[s] = 0.f;
#pragma unroll 4
            for (int k = 0; k < COND; k++) {
                float w = W0[k * D1 + t];
#pragma unroll
                for (int s = 0; s < 8; s++) acc[s] = fmaf(xs[s][k], w, acc[s]);
            }
            float bb = B0[t];
#pragma unroll
            for (int s = 0; s < 8; s++) h1s[s][t] = fmaxf(acc[s] + bb, 0.f);
        }
        __syncthreads();

        { // L2
            float a0[8], a1[8];
#pragma unroll
            for (int s = 0; s < 8; s++) { a0[s] = 0.f; a1[s] = 0.f; }
#pragma unroll 4
            for (int k = 0; k < D1; k++) {
                float w0 = W1[k * D2 + t];
                float w1 = W1[k * D2 + t + 256];
#pragma unroll
                for (int s = 0; s < 8; s++) {
                    float h = h1s[s][k];
                    a0[s] = fmaf(h, w0, a0[s]);
                    a1[s] = fmaf(h, w1, a1[s]);
                }
            }
            float b0v = B1[t], b1v = B1[t + 256];
#pragma unroll
            for (int s = 0; s < 8; s++) {
                h2s[s][t]       = fmaxf(a0[s] + b0v, 0.f);
                h2s[s][t + 256] = fmaxf(a1[s] + b1v, 0.f);
            }
        }
        __syncthreads();

        { // L3 (this block's half)
            float acc[2][8];
#pragma unroll
            for (int q = 0; q < 2; q++)
#pragma unroll
                for (int s = 0; s < 8; s++) acc[q][s] = 0.f;
            int c0 = t + (qh * 2 + 0) * 256;
            int c1 = t + (qh * 2 + 1) * 256;
#pragma unroll 2
            for (int k = 0; k < D2; k++) {
                float w0 = W2[k * D3 + c0];
                float w1 = W2[k * D3 + c1];
#pragma unroll
                for (int s = 0; s < 8; s++) {
                    float h = h2s[s][k];
                    acc[0][s] = fmaf(h, w0, acc[0][s]);
                    acc[1][s] = fmaf(h, w1, acc[1][s]);
                }
            }
#pragma unroll
            for (int q = 0; q < 2; q++) {
                int neuron = t + (qh * 2 + q) * 256;
                float bq = B2[neuron];
#pragma unroll
                for (int s = 0; s < 8; s++) {
                    if (own[s]) {
                        float v = fmaxf(acc[q][s] + bq, 0.f);
                        __nv_bfloat16 hi = __float2bfloat16_rn(v);
                        __nv_bfloat16 lo = __float2bfloat16_rn(v - __bfloat162float(hi));
                        g_h3hi[bi[s] * D3 + neuron] = hi;
                        g_h3lo[bi[s] * D3 + neuron] = lo;
                    }
                }
            }
        }
        __syncthreads();
    }
}

// ---------------- kernel C: margin GEMM via mma.sync bf16 (4-term hi/lo split) ----------------
// grid (255, 8): x = 128-edge tile; y: expert = y>>2, row tile = y&3 (128 rows)
// smem: A_hi, A_lo, B_hi, B_lo tiles of [128][40] bf16 (80 B rows), single-buffered.
#define TSTRIDE 80      // bytes per smem row (40 bf16)
#define A_HI 0
#define A_LO 10240
#define B_HI 20480
#define B_LO 30720
#define BYTESTRIDE 136

__global__ __launch_bounds__(256) void k_gemm(
    const float* __restrict__ gumbel,
    const float* __restrict__ bw3, const float* __restrict__ bb3,
    const float* __restrict__ sw3, const float* __restrict__ sb3)
{
    __shared__ __align__(16) char sbuf[40960];
    __shared__ int batch_s[128];
    __shared__ float bdiff_s[128];

    int t = threadIdx.x;
    int wid = t >> 5;
    int lane = t & 31;
    int expert = blockIdx.y >> 2;
    int tile = blockIdx.y & 3;
    int nbig = g_cnt[0];
    int cnt = expert ? (B - nbig) : nbig;
    int base = expert ? nbig : 0;
    int rbase = tile * 128;
    int rows = cnt - rbase;
    if (rows <= 0) return;
    if (rows > 128) rows = 128;
    int n0 = blockIdx.x * 128;

    const float* W3 = expert ? sw3 : bw3;
    const float* B3 = expert ? sb3 : bb3;

    if (t < 128) {
        int r = t < rows ? t : (rows - 1);
        batch_s[t] = g_perm[base + rbase + r];
        float2 bp = *(const float2*)(B3 + 2 * (n0 + t));
        bdiff_s[t] = bp.x - bp.y;
    }
    __syncthreads();

    float acc[4][4][4];
#pragma unroll
    for (int i = 0; i < 4; i++)
#pragma unroll
        for (int jj = 0; jj < 4; jj++)
#pragma unroll
            for (int r = 0; r < 4; r++) acc[i][jj][r] = 0.f;

    const uint32_t sb0 = smem_u32(sbuf);
    const int mbase = (wid >> 2) * 64;
    const int nbase = (wid & 3) * 32;
    const int lrow = lane & 15;
    const int lsel = lane >> 4;

    // A-load indices: i in {t, t+256}: r = i>>2 (row), seg = i&3
    const int ar0 = t >> 2, as0 = t & 3;
    const int ar1 = (t + 256) >> 2, as1 = (t + 256) & 3;
    const size_t abase0 = (size_t)batch_s[ar0] * D3 + as0 * 8;
    const size_t abase1 = (size_t)batch_s[ar1] * D3 + as1 * 8;
    // B-load indices: e = t&127, kg = t>>7
    const int be = t & 127;
    const int bkg = t >> 7;

    for (int j = 0; j < 32; j++) {
        // ---- A chunk: 128 rows x 32 bf16 (hi & lo) ----
        {
            uint4 vh0 = *(const uint4*)(g_h3hi + abase0 + j * 32);
            uint4 vl0 = *(const uint4*)(g_h3lo + abase0 + j * 32);
            uint4 vh1 = *(const uint4*)(g_h3hi + abase1 + j * 32);
            uint4 vl1 = *(const uint4*)(g_h3lo + abase1 + j * 32);
            *(uint4*)(sbuf + A_HI + ar0 * TSTRIDE + as0 * 16) = vh0;
            *(uint4*)(sbuf + A_LO + ar0 * TSTRIDE + as0 * 16) = vl0;
            *(uint4*)(sbuf + A_HI + ar1 * TSTRIDE + as1 * 16) = vh1;
            *(uint4*)(sbuf + A_LO + ar1 * TSTRIDE + as1 * 16) = vl1;
        }
        // ---- B chunk: wdiff -> bf16 hi/lo, [edge][k] ----
#pragma unroll
        for (int p = 0; p < 2; p++) {
            int kbase = (p * 2 + bkg) * 8;
            union { __nv_bfloat16 a[8]; uint4 v; } ph, pl;
#pragma unroll
            for (int jj = 0; jj < 8; jj++) {
                float2 w = *(const float2*)(W3 + (size_t)(j * 32 + kbase + jj) * OUT2 + 2 * (n0 + be));
                float d = w.x - w.y;
                __nv_bfloat16 hi = __float2bfloat16_rn(d);
                __nv_bfloat16 lo = __float2bfloat16_rn(d - __bfloat162float(hi));
                ph.a[jj] = hi; pl.a[jj] = lo;
            }
            *(uint4*)(sbuf + B_HI + be * TSTRIDE + kbase * 2) = ph.v;
            *(uint4*)(sbuf + B_LO + be * TSTRIDE + kbase * 2) = pl.v;
        }
        __syncthreads();

        // ---- MMA: 2 k16 steps x 4 terms ----
#pragma unroll
        for (int ks = 0; ks < 2; ks++) {
            uint32_t koff = (uint32_t)((ks * 16 + lsel * 8) * 2);
            uint32_t bh[2][4], bl[2][4];
#pragma unroll
            for (int bg = 0; bg < 2; bg++) {
                uint32_t rowoff = (uint32_t)((nbase + bg * 16 + lrow) * TSTRIDE) + koff;
                ldm_x4(bh[bg][0], bh[bg][1], bh[bg][2], bh[bg][3], sb0 + B_HI + rowoff);
                ldm_x4(bl[bg][0], bl[bg][1], bl[bg][2], bl[bg][3], sb0 + B_LO + rowoff);
            }
            uint32_t af[4][4];
            // A hi: terms (hi,hi) and (hi,lo)
#pragma unroll
            for (int mf = 0; mf < 4; mf++) {
                uint32_t rowoff = (uint32_t)((mbase + mf * 16 + lrow) * TSTRIDE) + koff;
                ldm_x4(af[mf][0], af[mf][1], af[mf][2], af[mf][3], sb0 + A_HI + rowoff);
            }
#pragma unroll
            for (int mf = 0; mf < 4; mf++)
#pragma unroll
                for (int nf = 0; nf < 4; nf++) {
                    int bg = nf >> 1, h = nf & 1;
                    mma_bf16(acc[mf][nf], af[mf][0], af[mf][1], af[mf][2], af[mf][3],
                             bh[bg][h], bh[bg][2 + h]);
                    mma_bf16(acc[mf][nf], af[mf][0], af[mf][1], af[mf][2], af[mf][3],
                             bl[bg][h], bl[bg][2 + h]);
                }
            // A lo: terms (lo,hi) and (lo,lo)
#pragma unroll
            for (int mf = 0; mf < 4; mf++) {
                uint32_t rowoff = (uint32_t)((mbase + mf * 16 + lrow) * TSTRIDE) + koff;
                ldm_x4(af[mf][0], af[mf][1], af[mf][2], af[mf][3], sb0 + A_LO + rowoff);
            }
#pragma unroll
            for (int mf = 0; mf < 4; mf++)
#pragma unroll
                for (int nf = 0; nf < 4; nf++) {
                    int bg = nf >> 1, h = nf & 1;
                    mma_bf16(acc[mf][nf], af[mf][0], af[mf][1], af[mf][2], af[mf][3],
                             bh[bg][h], bh[bg][2 + h]);
                    mma_bf16(acc[mf][nf], af[mf][0], af[mf][1], af[mf][2], af[mf][3],
                             bl[bg][h], bl[bg][2 + h]);
                }
        }
        __syncthreads();
    }

    // ---- epilogue: margin = acc + bdiff + gumbel diff; bits -> smem -> gmem ----
    int g = lane >> 2, tid = lane & 3;
#pragma unroll
    for (int mf = 0; mf < 4; mf++) {
#pragma unroll
        for (int h = 0; h < 2; h++) {
            int mrow = mbase + mf * 16 + g + h * 8;
            const float2* gpr = (const float2*)(gumbel + (size_t)batch_s[mrow] * OUT2 + 2 * n0);
#pragma unroll
            for (int nf = 0; nf < 4; nf++) {
                int ncol = nbase + nf * 8 + 2 * tid;
                float2 gA = gpr[ncol];
                float2 gB = gpr[ncol + 1];
                float m0 = acc[mf][nf][h * 2 + 0] + bdiff_s[ncol]     + (gA.x - gA.y);
                float m1 = acc[mf][nf][h * 2 + 1] + bdiff_s[ncol + 1] + (gB.x - gB.y);
                unsigned short v = (unsigned short)((m0 >= 0.f ? 1 : 0) | ((m1 >= 0.f ? 1 : 0) << 8));
                *(unsigned short*)(sbuf + mrow * BYTESTRIDE + ncol) = v;
            }
        }
    }
    __syncthreads();

    // flush: coalesced uint2 per 8 edges
#pragma unroll
    for (int pass = 0; pass < 8; pass++) {
        int idx = pass * 256 + t;
        int r = idx >> 4, seg = idx & 15;
        if (r < rows) {
            uint2 v = *(const uint2*)(sbuf + r * BYTESTRIDE + seg * 8);
            *(uint2*)(g_edges + (size_t)batch_s[r] * EPAD + n0 + seg * 8) = v;
        }
    }
}

// ---------------- kernel D: expand bits -> symmetric 256x256 fp32 ----------------
__global__ __launch_bounds__(256) void k_expand(float* __restrict__ out) {
    const int pi_ = blockIdx.y;
    int I0, J0;
    {
        const int pI[10] = {0,0,0,0,1,1,1,2,2,3};
        const int pJ[10] = {0,1,2,3,1,2,3,2,3,3};
        I0 = pI[pi_] * 64; J0 = pJ[pi_] * 64;
    }
    int b = blockIdx.x;
    __shared__ unsigned char s[64][68];
    const unsigned char* eb = g_edges + (size_t)b * EPAD;
    float* ob = out + (size_t)b * (NN * NN);
    int t = threadIdx.x;
    bool diag = (I0 == J0);

    int col = t & 63;
    int rg = t >> 6;
#pragma unroll 4
    for (int c = 0; c < 16; c++) {
        int il = rg * 16 + c;
        int i = I0 + il;
        int j = J0 + col;
        unsigned char v = 0;
        if (j > i) v = eb[(size_t)i * (511 - i) / 2 + (j - i - 1)];
        s[il][col] = v;
    }
    __syncthreads();

    int ilq = t >> 4;
    int jl = (t & 15) * 4;
#pragma unroll
    for (int p = 0; p < 4; p++) {
        int il = p * 16 + ilq;
        float4 v;
        if (diag) {
            int i = I0 + il;
            float vv[4];
#pragma unroll
            for (int c = 0; c < 4; c++) {
                int jj = J0 + jl + c;
                unsigned char u = (jj > i) ? s[il][jl + c] : ((jj < i) ? s[jl + c][il] : 0);
                vv[c] = (float)u;
            }
            v = make_float4(vv[0], vv[1], vv[2], vv[3]);
        } else {
            v = make_float4((float)s[il][jl], (float)s[il][jl + 1],
                            (float)s[il][jl + 2], (float)s[il][jl + 3]);
        }
        *(float4*)&ob[(I0 + il) * NN + J0 + jl] = v;
        if (!diag) {
            float4 w = make_float4((float)s[jl][il], (float)s[jl + 1][il],
                                   (float)s[jl + 2][il], (float)s[jl + 3][il]);
            *(float4*)&ob[(J0 + il) * NN + I0 + jl] = w;
        }
    }
}

// ---------------- launch ----------------
extern "C" void kernel_launch(void* const* d_in, const int* in_sizes, int n_in,
                              void* d_out, int out_size) {
    const float* x      = (const float*)d_in[0];
    const float* gumbel = (const float*)d_in[1];

    const float *bw[4], *bb[4], *sw[4], *sb[4];
    if (in_sizes[4] == 16384) {
        for (int l = 0; l < 4; l++) {
            bw[l] = (const float*)d_in[2 + 4 * l];
            bb[l] = (const float*)d_in[3 + 4 * l];
            sw[l] = (const float*)d_in[4 + 4 * l];
            sb[l] = (const float*)d_in[5 + 4 * l];
        }
    } else {
        for (int l = 0; l < 4; l++) {
            bw[l] = (const float*)d_in[2 + 2 * l];
            bb[l] = (const float*)d_in[3 + 2 * l];
            sw[l] = (const float*)d_in[10 + 2 * l];
            sb[l] = (const float*)d_in[11 + 2 * l];
        }
    }
    float* out = (float*)d_out;

    k_group<<<1, B>>>(x);
    k_hidden<<<dim3(64, 2), 256>>>(x,
        bw[0], bb[0], bw[1], bb[1], bw[2], bb[2],
        sw[0], sb[0], sw[1], sb[1], sw[2], sb[2]);
    k_gemm<<<dim3(255, 8), 256>>>(gumbel, bw[3], bb[3], sw[3], sb[3]);
    k_expand<<<dim3(B, 10), 256>>>(out);
}

// round 5
// speedup vs baseline: 2.2127x; 1.0923x over previous
#include <cuda_runtime.h>
#include <cuda_bf16.h>
#include <cstdint>

#define B 512
#define COND 64
#define NN 256
#define NE 32640
#define OUT2 65280
#define D1 256
#define D2 512
#define D3 1024
#define EPAD 32768

// ---------------- scratch ----------------
__device__ __nv_bfloat16 g_h3hi[B * D3];
__device__ __nv_bfloat16 g_h3lo[B * D3];
__device__ int g_perm[B];
__device__ int g_cnt[2];
__device__ unsigned char g_edges[B * EPAD];

// ---------------- helpers ----------------
__device__ __forceinline__ uint32_t smem_u32(const void* p) {
    uint32_t a;
    asm("{ .reg .u64 t; cvta.to.shared.u64 t, %1; cvt.u32.u64 %0, t; }" : "=r"(a) : "l"(p));
    return a;
}
__device__ __forceinline__ void ldm_x4(uint32_t& r0, uint32_t& r1, uint32_t& r2, uint32_t& r3,
                                       uint32_t addr) {
    asm volatile("ldmatrix.sync.aligned.m8n8.x4.shared.b16 {%0,%1,%2,%3}, [%4];"
                 : "=r"(r0), "=r"(r1), "=r"(r2), "=r"(r3) : "r"(addr));
}
__device__ __forceinline__ void mma_bf16(float* c, uint32_t a0, uint32_t a1, uint32_t a2,
                                         uint32_t a3, uint32_t b0, uint32_t b1) {
    asm volatile(
        "mma.sync.aligned.m16n8k16.row.col.f32.bf16.bf16.f32 "
        "{%0,%1,%2,%3}, {%4,%5,%6,%7}, {%8,%9}, {%0,%1,%2,%3};"
        : "+f"(c[0]), "+f"(c[1]), "+f"(c[2]), "+f"(c[3])
        : "r"(a0), "r"(a1), "r"(a2), "r"(a3), "r"(b0), "r"(b1));
}

// ---------------- kernel A: partition by expert ----------------
__global__ void k_group(const float* __restrict__ x) {
    __shared__ int cnt[2];
    int t = threadIdx.x;
    if (t < 2) cnt[t] = 0;
    __syncthreads();
    int big = (x[t * COND] > 0.0f) ? 1 : 0;
    int p = atomicAdd(&cnt[big ? 0 : 1], 1);
    g_perm[big ? p : (B - 1 - p)] = t;
    __syncthreads();
    if (t == 0) { g_cnt[0] = cnt[0]; g_cnt[1] = cnt[1]; }
}

// ---------------- kernel B: trunk 64->256->512->1024, outputs bf16 hi/lo ----------------
__global__ __launch_bounds__(256) void k_hidden(
    const float* __restrict__ x,
    const float* __restrict__ bw0, const float* __restrict__ bb0,
    const float* __restrict__ bw1, const float* __restrict__ bb1,
    const float* __restrict__ bw2, const float* __restrict__ bb2,
    const float* __restrict__ sw0, const float* __restrict__ sb0,
    const float* __restrict__ sw1, const float* __restrict__ sb1,
    const float* __restrict__ sw2, const float* __restrict__ sb2)
{
    __shared__ float xs[8][COND];
    __shared__ float h1s[8][D1];
    __shared__ float h2s[8][D2];
    __shared__ int bi[8];

    int t = threadIdx.x;
    int g = blockIdx.x;
    int qh = blockIdx.y;
    if (t < 8) bi[t] = g_perm[g * 8 + t];
    __syncthreads();
    int nbig = g_cnt[0];

    for (int i = t; i < 8 * COND; i += 256) {
        int s = i >> 6, k = i & 63;
        xs[s][k] = x[bi[s] * COND + k];
    }
    __syncthreads();

    for (int ex = 0; ex < 2; ex++) {
        bool own[8]; bool anyown = false;
#pragma unroll
        for (int s = 0; s < 8; s++) {
            own[s] = (((g * 8 + s) < nbig ? 0 : 1) == ex);
            anyown |= own[s];
        }
        if (!anyown) continue;

        const float* W0 = ex ? sw0 : bw0; const float* B0 = ex ? sb0 : bb0;
        const float* W1 = ex ? sw1 : bw1; const float* B1 = ex ? sb1 : bb1;
        const float* W2 = ex ? sw2 : bw2; const float* B2 = ex ? sb2 : bb2;

        { // L1
            float acc[8];
#pragma unroll
            for (int s = 0; s < 8; s++) acc[s] = 0.f;
#pragma unroll 4
            for (int k = 0; k < COND; k++) {
                float w = W0[k * D1 + t];
#pragma unroll
                for (int s = 0; s < 8; s++) acc[s] = fmaf(xs[s][k], w, acc[s]);
            }
            float bb = B0[t];
#pragma unroll
            for (int s = 0; s < 8; s++) h1s[s][t] = fmaxf(acc[s] + bb, 0.f);
        }
        __syncthreads();

        { // L2
            float a0[8], a1[8];
#pragma unroll
            for (int s = 0; s < 8; s++) { a0[s] = 0.f; a1[s] = 0.f; }
#pragma unroll 4
            for (int k = 0; k < D1; k++) {
                float w0 = W1[k * D2 + t];
                float w1 = W1[k * D2 + t + 256];
#pragma unroll
                for (int s = 0; s < 8; s++) {
                    float h = h1s[s][k];
                    a0[s] = fmaf(h, w0, a0[s]);
                    a1[s] = fmaf(h, w1, a1[s]);
                }
            }
            float b0v = B1[t], b1v = B1[t + 256];
#pragma unroll
            for (int s = 0; s < 8; s++) {
                h2s[s][t]       = fmaxf(a0[s] + b0v, 0.f);
                h2s[s][t + 256] = fmaxf(a1[s] + b1v, 0.f);
            }
        }
        __syncthreads();

        { // L3 (this block's half)
            float acc[2][8];
#pragma unroll
            for (int q = 0; q < 2; q++)
#pragma unroll
                for (int s = 0; s < 8; s++) acc[q][s] = 0.f;
            int c0 = t + (qh * 2 + 0) * 256;
            int c1 = t + (qh * 2 + 1) * 256;
#pragma unroll 2
            for (int k = 0; k < D2; k++) {
                float w0 = W2[k * D3 + c0];
                float w1 = W2[k * D3 + c1];
#pragma unroll
                for (int s = 0; s < 8; s++) {
                    float h = h2s[s][k];
                    acc[0][s] = fmaf(h, w0, acc[0][s]);
                    acc[1][s] = fmaf(h, w1, acc[1][s]);
                }
            }
#pragma unroll
            for (int q = 0; q < 2; q++) {
                int neuron = t + (qh * 2 + q) * 256;
                float bq = B2[neuron];
#pragma unroll
                for (int s = 0; s < 8; s++) {
                    if (own[s]) {
                        float v = fmaxf(acc[q][s] + bq, 0.f);
                        __nv_bfloat16 hi = __float2bfloat16_rn(v);
                        __nv_bfloat16 lo = __float2bfloat16_rn(v - __bfloat162float(hi));
                        g_h3hi[bi[s] * D3 + neuron] = hi;
                        g_h3lo[bi[s] * D3 + neuron] = lo;
                    }
                }
            }
        }
        __syncthreads();
    }
}

// ---------------- kernel C: margin GEMM via mma.sync bf16 (3-term hi/lo split) ----------------
// grid (255, 8); register-prefetch pipeline over 32 K-chunks of 32.
#define TSTRIDE 80
#define A_HI 0
#define A_LO 10240
#define B_HI 20480
#define B_LO 30720
#define BYTESTRIDE 136

__global__ __launch_bounds__(256) void k_gemm(
    const float* __restrict__ gumbel,
    const float* __restrict__ bw3, const float* __restrict__ bb3,
    const float* __restrict__ sw3, const float* __restrict__ sb3)
{
    __shared__ __align__(16) char sbuf[40960];
    __shared__ int batch_s[128];
    __shared__ float bdiff_s[128];

    int t = threadIdx.x;
    int wid = t >> 5;
    int lane = t & 31;
    int expert = blockIdx.y >> 2;
    int tile = blockIdx.y & 3;
    int nbig = g_cnt[0];
    int cnt = expert ? (B - nbig) : nbig;
    int base = expert ? nbig : 0;
    int rbase = tile * 128;
    int rows = cnt - rbase;
    if (rows <= 0) return;
    if (rows > 128) rows = 128;
    int n0 = blockIdx.x * 128;

    const float* W3 = expert ? sw3 : bw3;
    const float* B3 = expert ? sb3 : bb3;

    if (t < 128) {
        int r = t < rows ? t : (rows - 1);
        batch_s[t] = g_perm[base + rbase + r];
        float2 bp = *(const float2*)(B3 + 2 * (n0 + t));
        bdiff_s[t] = bp.x - bp.y;
    }
    __syncthreads();

    float acc[4][4][4];
#pragma unroll
    for (int i = 0; i < 4; i++)
#pragma unroll
        for (int jj = 0; jj < 4; jj++)
#pragma unroll
            for (int r = 0; r < 4; r++) acc[i][jj][r] = 0.f;

    const uint32_t sb0 = smem_u32(sbuf);
    const int mbase = (wid >> 2) * 64;
    const int nbase = (wid & 3) * 32;
    const int lrow = lane & 15;
    const int lsel = lane >> 4;

    const int ar0 = t >> 2, as0 = t & 3;
    const int ar1 = (t + 256) >> 2, as1 = (t + 256) & 3;
    const size_t abase0 = (size_t)batch_s[ar0] * D3 + as0 * 8;
    const size_t abase1 = (size_t)batch_s[ar1] * D3 + as1 * 8;
    const int be = t & 127;
    const int bkg = t >> 7;
    const float* wbase = W3 + 2 * (n0 + be);

    // prefetch registers
    uint4 vh0, vl0, vh1, vl1;
    float2 wreg[16];

    // prologue: fetch chunk 0
    {
        vh0 = *(const uint4*)(g_h3hi + abase0);
        vl0 = *(const uint4*)(g_h3lo + abase0);
        vh1 = *(const uint4*)(g_h3hi + abase1);
        vl1 = *(const uint4*)(g_h3lo + abase1);
#pragma unroll
        for (int p = 0; p < 2; p++)
#pragma unroll
            for (int jj = 0; jj < 8; jj++)
                wreg[p * 8 + jj] = *(const float2*)(wbase + (size_t)((p * 2 + bkg) * 8 + jj) * OUT2);
    }

    for (int j = 0; j < 32; j++) {
        __syncthreads();   // previous iteration's MMA consumers done
        // ---- store prefetched A chunk ----
        *(uint4*)(sbuf + A_HI + ar0 * TSTRIDE + as0 * 16) = vh0;
        *(uint4*)(sbuf + A_LO + ar0 * TSTRIDE + as0 * 16) = vl0;
        *(uint4*)(sbuf + A_HI + ar1 * TSTRIDE + as1 * 16) = vh1;
        *(uint4*)(sbuf + A_LO + ar1 * TSTRIDE + as1 * 16) = vl1;
        // ---- convert + store prefetched B chunk ----
#pragma unroll
        for (int p = 0; p < 2; p++) {
            int kbase = (p * 2 + bkg) * 8;
            union { __nv_bfloat16 a[8]; uint4 v; } ph, pl;
#pragma unroll
            for (int jj = 0; jj < 8; jj++) {
                float2 w = wreg[p * 8 + jj];
                float d = w.x - w.y;
                __nv_bfloat16 hi = __float2bfloat16_rn(d);
                __nv_bfloat16 lo = __float2bfloat16_rn(d - __bfloat162float(hi));
                ph.a[jj] = hi; pl.a[jj] = lo;
            }
            *(uint4*)(sbuf + B_HI + be * TSTRIDE + kbase * 2) = ph.v;
            *(uint4*)(sbuf + B_LO + be * TSTRIDE + kbase * 2) = pl.v;
        }
        __syncthreads();

        // ---- prefetch next chunk into registers (latency hides behind MMA) ----
        if (j < 31) {
            size_t koff = (size_t)(j + 1) * 32;
            vh0 = *(const uint4*)(g_h3hi + abase0 + koff);
            vl0 = *(const uint4*)(g_h3lo + abase0 + koff);
            vh1 = *(const uint4*)(g_h3hi + abase1 + koff);
            vl1 = *(const uint4*)(g_h3lo + abase1 + koff);
#pragma unroll
            for (int p = 0; p < 2; p++)
#pragma unroll
                for (int jj = 0; jj < 8; jj++)
                    wreg[p * 8 + jj] =
                        *(const float2*)(wbase + (koff + (p * 2 + bkg) * 8 + jj) * OUT2);
        }

        // ---- MMA: 2 k16 steps x 3 terms ----
#pragma unroll
        for (int ks = 0; ks < 2; ks++) {
            uint32_t koff2 = (uint32_t)((ks * 16 + lsel * 8) * 2);
            uint32_t bh[2][4], bl[2][4];
#pragma unroll
            for (int bg = 0; bg < 2; bg++) {
                uint32_t rowoff = (uint32_t)((nbase + bg * 16 + lrow) * TSTRIDE) + koff2;
                ldm_x4(bh[bg][0], bh[bg][1], bh[bg][2], bh[bg][3], sb0 + B_HI + rowoff);
                ldm_x4(bl[bg][0], bl[bg][1], bl[bg][2], bl[bg][3], sb0 + B_LO + rowoff);
            }
            uint32_t af[4][4];
            // A hi: terms (hi,hi) and (hi,lo)
#pragma unroll
            for (int mf = 0; mf < 4; mf++) {
                uint32_t rowoff = (uint32_t)((mbase + mf * 16 + lrow) * TSTRIDE) + koff2;
                ldm_x4(af[mf][0], af[mf][1], af[mf][2], af[mf][3], sb0 + A_HI + rowoff);
            }
#pragma unroll
            for (int mf = 0; mf < 4; mf++)
#pragma unroll
                for (int nf = 0; nf < 4; nf++) {
                    int bg = nf >> 1, h = nf & 1;
                    mma_bf16(acc[mf][nf], af[mf][0], af[mf][1], af[mf][2], af[mf][3],
                             bh[bg][h], bh[bg][2 + h]);
                    mma_bf16(acc[mf][nf], af[mf][0], af[mf][1], af[mf][2], af[mf][3],
                             bl[bg][h], bl[bg][2 + h]);
                }
            // A lo: term (lo,hi)
#pragma unroll
            for (int mf = 0; mf < 4; mf++) {
                uint32_t rowoff = (uint32_t)((mbase + mf * 16 + lrow) * TSTRIDE) + koff2;
                ldm_x4(af[mf][0], af[mf][1], af[mf][2], af[mf][3], sb0 + A_LO + rowoff);
            }
#pragma unroll
            for (int mf = 0; mf < 4; mf++)
#pragma unroll
                for (int nf = 0; nf < 4; nf++) {
                    int bg = nf >> 1, h = nf & 1;
                    mma_bf16(acc[mf][nf], af[mf][0], af[mf][1], af[mf][2], af[mf][3],
                             bh[bg][h], bh[bg][2 + h]);
                }
        }
    }
    __syncthreads();

    // ---- epilogue: margin = acc + bdiff + gumbel diff; bits -> smem -> gmem ----
    int g = lane >> 2, tid4 = lane & 3;
#pragma unroll
    for (int mf = 0; mf < 4; mf++) {
#pragma unroll
        for (int h = 0; h < 2; h++) {
            int mrow = mbase + mf * 16 + g + h * 8;
            const float2* gpr = (const float2*)(gumbel + (size_t)batch_s[mrow] * OUT2 + 2 * n0);
#pragma unroll
            for (int nf = 0; nf < 4; nf++) {
                int ncol = nbase + nf * 8 + 2 * tid4;
                float2 gA = gpr[ncol];
                float2 gB = gpr[ncol + 1];
                float m0 = acc[mf][nf][h * 2 + 0] + bdiff_s[ncol]     + (gA.x - gA.y);
                float m1 = acc[mf][nf][h * 2 + 1] + bdiff_s[ncol + 1] + (gB.x - gB.y);
                unsigned short v = (unsigned short)((m0 >= 0.f ? 1 : 0) | ((m1 >= 0.f ? 1 : 0) << 8));
                *(unsigned short*)(sbuf + mrow * BYTESTRIDE + ncol) = v;
            }
        }
    }
    __syncthreads();

#pragma unroll
    for (int pass = 0; pass < 8; pass++) {
        int idx = pass * 256 + t;
        int r = idx >> 4, seg = idx & 15;
        if (r < rows) {
            uint2 v = *(const uint2*)(sbuf + r * BYTESTRIDE + seg * 8);
            *(uint2*)(g_edges + (size_t)batch_s[r] * EPAD + n0 + seg * 8) = v;
        }
    }
}

// ---------------- kernel D: expand bits -> symmetric 256x256 fp32 ----------------
__global__ __launch_bounds__(256) void k_expand(float* __restrict__ out) {
    const int pi_ = blockIdx.y;
    int I0, J0;
    {
        const int pI[10] = {0,0,0,0,1,1,1,2,2,3};
        const int pJ[10] = {0,1,2,3,1,2,3,2,3,3};
        I0 = pI[pi_] * 64; J0 = pJ[pi_] * 64;
    }
    int b = blockIdx.x;
    __shared__ unsigned char s[64][68];
    const unsigned char* eb = g_edges + (size_t)b * EPAD;
    float* ob = out + (size_t)b * (NN * NN);
    int t = threadIdx.x;
    bool diag = (I0 == J0);

    int col = t & 63;
    int rg = t >> 6;
#pragma unroll 4
    for (int c = 0; c < 16; c++) {
        int il = rg * 16 + c;
        int i = I0 + il;
        int j = J0 + col;
        unsigned char v = 0;
        if (j > i) v = eb[(size_t)i * (511 - i) / 2 + (j - i - 1)];
        s[il][col] = v;
    }
    __syncthreads();

    int ilq = t >> 4;
    int jl = (t & 15) * 4;
#pragma unroll
    for (int p = 0; p < 4; p++) {
        int il = p * 16 + ilq;
        float4 v;
        if (diag) {
            int i = I0 + il;
            float vv[4];
#pragma unroll
            for (int c = 0; c < 4; c++) {
                int jj = J0 + jl + c;
                unsigned char u = (jj > i) ? s[il][jl + c] : ((jj < i) ? s[jl + c][il] : 0);
                vv[c] = (float)u;
            }
            v = make_float4(vv[0], vv[1], vv[2], vv[3]);
        } else {
            v = make_float4((float)s[il][jl], (float)s[il][jl + 1],
                            (float)s[il][jl + 2], (float)s[il][jl + 3]);
        }
        *(float4*)&ob[(I0 + il) * NN + J0 + jl] = v;
        if (!diag) {
            float4 w = make_float4((float)s[jl][il], (float)s[jl + 1][il],
                                   (float)s[jl + 2][il], (float)s[jl + 3][il]);
            *(float4*)&ob[(J0 + il) * NN + I0 + jl] = w;
        }
    }
}

// ---------------- launch ----------------
extern "C" void kernel_launch(void* const* d_in, const int* in_sizes, int n_in,
                              void* d_out, int out_size) {
    const float* x      = (const float*)d_in[0];
    const float* gumbel = (const float*)d_in[1];

    const float *bw[4], *bb[4], *sw[4], *sb[4];
    if (in_sizes[4] == 16384) {
        for (int l = 0; l < 4; l++) {
            bw[l] = (const float*)d_in[2 + 4 * l];
            bb[l] = (const float*)d_in[3 + 4 * l];
            sw[l] = (const float*)d_in[4 + 4 * l];
            sb[l] = (const float*)d_in[5 + 4 * l];
        }
    } else {
        for (int l = 0; l < 4; l++) {
            bw[l] = (const float*)d_in[2 + 2 * l];
            bb[l] = (const float*)d_in[3 + 2 * l];
            sw[l] = (const float*)d_in[10 + 2 * l];
            sb[l] = (const float*)d_in[11 + 2 * l];
        }
    }
    float* out = (float*)d_out;

    k_group<<<1, B>>>(x);
    k_hidden<<<dim3(64, 2), 256>>>(x,
        bw[0], bb[0], bw[1], bb[1], bw[2], bb[2],
        sw[0], sb[0], sw[1], sb[1], sw[2], sb[2]);
    k_gemm<<<dim3(255, 8), 256>>>(gumbel, bw[3], bb[3], sw[3], sb[3]);
    k_expand<<<dim3(B, 10), 256>>>(out);
}